// round 2
// baseline (speedup 1.0000x reference)
#include <cuda_runtime.h>
#include <math.h>

#define BB 4
#define SS 4096
#define HH 8
#define DD 64
#define HD (HH*DD)
#define SCALE 0.125f
#define NBH (BB*HH)          // 32 (b,h) pairs
#define CH 32                // leaves per chunk
#define CPB (SS/CH)          // 128 chunks per bh
#define HI_NODES 254         // levels 5..11 per bh: 128+64+32+16+8+4+2

// Global storage for tree levels 5..11 only (~2MB each, L2-resident).
// Per-bh layout: level5 @0 (128), l6 @128 (64), l7 @192 (32), l8 @224 (16),
//                l9 @240 (8), l10 @248 (4), l11 @252 (2).
__device__ float g_hiK[(size_t)NBH * HI_NODES * DD];
__device__ float g_hiV[(size_t)NBH * HI_NODES * DD];

// Softmax-pool two children rows into a parent row. Warp-collective,
// each lane owns dims {2*lane, 2*lane+1}.
__device__ __forceinline__ void poolp(const float* __restrict__ kc0,
                                      const float* __restrict__ kc1,
                                      const float* __restrict__ vc0,
                                      const float* __restrict__ vc1,
                                      float* __restrict__ kout,
                                      float* __restrict__ vout, int lane) {
    float2 a  = *(const float2*)(kc0 + 2 * lane);
    float2 b  = *(const float2*)(kc1 + 2 * lane);
    float2 va = *(const float2*)(vc0 + 2 * lane);
    float2 vb = *(const float2*)(vc1 + 2 * lane);
    float2 kp;
    kp.x = 0.5f * (a.x + b.x);
    kp.y = 0.5f * (a.y + b.y);
    float ds = kp.x * kp.x + kp.y * kp.y;
    float d0 = kp.x * a.x + kp.y * a.y;
    float d1 = kp.x * b.x + kp.y * b.y;
#pragma unroll
    for (int o = 16; o; o >>= 1) {
        ds += __shfl_xor_sync(0xffffffffu, ds, o);
        d0 += __shfl_xor_sync(0xffffffffu, d0, o);
        d1 += __shfl_xor_sync(0xffffffffu, d1, o);
    }
    float ss = ds * SCALE, s0 = d0 * SCALE, s1 = d1 * SCALE;
    float m  = fmaxf(ss, fmaxf(s0, s1));
    float es = __expf(ss - m), e0 = __expf(s0 - m), e1 = __expf(s1 - m);
    float inv = 1.0f / (es + e0 + e1 + 1e-9f);
    float hes = 0.5f * es;
    float2 vp;
    vp.x = (hes * (va.x + vb.x) + e0 * va.x + e1 * vb.x) * inv;
    vp.y = (hes * (va.y + vb.y) + e0 * va.y + e1 * vb.y) * inv;
    *(float2*)(kout + 2 * lane) = kp;
    *(float2*)(vout + 2 * lane) = vp;
}

// Shared layout (rows of 64 floats):
//  rows  0..31 : leaves
//  rows 32..47 : tree level 1 (16)
//  rows 48..55 : tree level 2 (8)
//  rows 56..59 : tree level 3 (4)
//  rows 60..61 : tree level 4 (2)
//  rows 62..68 : hi nodes, slot j -> level 5+j (attn kernel only)
#define R_TREE1 32
#define R_TREE2 48
#define R_TREE3 56
#define R_TREE4 60
#define R_HI    62
#define NROWS   69

// Build levels 1..4 of the chunk subtree in smem (16 warps? no: nwarps=8).
__device__ __forceinline__ void build_chunk_tree(float* smK, float* smV,
                                                 int warp, int lane) {
    // level 1: 16 pools
#pragma unroll
    for (int j = warp; j < 16; j += 8)
        poolp(smK + (2 * j) * DD, smK + (2 * j + 1) * DD,
              smV + (2 * j) * DD, smV + (2 * j + 1) * DD,
              smK + (R_TREE1 + j) * DD, smV + (R_TREE1 + j) * DD, lane);
    __syncthreads();
    // level 2: 8 pools
    if (warp < 8)
        poolp(smK + (R_TREE1 + 2 * warp) * DD, smK + (R_TREE1 + 2 * warp + 1) * DD,
              smV + (R_TREE1 + 2 * warp) * DD, smV + (R_TREE1 + 2 * warp + 1) * DD,
              smK + (R_TREE2 + warp) * DD, smV + (R_TREE2 + warp) * DD, lane);
    __syncthreads();
    // level 3: 4 pools
    if (warp < 4)
        poolp(smK + (R_TREE2 + 2 * warp) * DD, smK + (R_TREE2 + 2 * warp + 1) * DD,
              smV + (R_TREE2 + 2 * warp) * DD, smV + (R_TREE2 + 2 * warp + 1) * DD,
              smK + (R_TREE3 + warp) * DD, smV + (R_TREE3 + warp) * DD, lane);
    __syncthreads();
    // level 4: 2 pools
    if (warp < 2)
        poolp(smK + (R_TREE3 + 2 * warp) * DD, smK + (R_TREE3 + 2 * warp + 1) * DD,
              smV + (R_TREE3 + 2 * warp) * DD, smV + (R_TREE3 + 2 * warp + 1) * DD,
              smK + (R_TREE4 + warp) * DD, smV + (R_TREE4 + warp) * DD, lane);
    __syncthreads();
}

// Pass 1: per 32-leaf chunk, compute the chunk's level-5 node -> g_hi.
__global__ __launch_bounds__(256) void build5(const float* __restrict__ k,
                                              const float* __restrict__ v) {
    __shared__ float smK[NROWS * DD], smV[NROWS * DD];
    int blk = blockIdx.x;            // bh*CPB + cc
    int cc  = blk & (CPB - 1);
    int bh  = blk >> 7;
    int b = bh >> 3, h = bh & 7;
    int tid = threadIdx.x, warp = tid >> 5, lane = tid & 31;

    size_t rowbase = ((size_t)(b * SS + cc * CH) * HH + h) * DD;
    const float4* k4 = (const float4*)(k + rowbase);
    const float4* v4 = (const float4*)(v + rowbase);
#pragma unroll
    for (int i = tid; i < CH * 16; i += 256) {
        int r = i >> 4, c = i & 15;
        ((float4*)smK)[i] = k4[r * (HD / 4) + c];
        ((float4*)smV)[i] = v4[r * (HD / 4) + c];
    }
    __syncthreads();

    build_chunk_tree(smK, smV, warp, lane);

    // level 5: one pool from tree level-4 rows -> global
    if (warp == 0) {
        size_t o = ((size_t)bh * HI_NODES + cc) * DD;
        poolp(smK + R_TREE4 * DD, smK + (R_TREE4 + 1) * DD,
              smV + R_TREE4 * DD, smV + (R_TREE4 + 1) * DD,
              g_hiK + o, g_hiV + o, lane);
    }
}

// Pass 2: per bh, build levels 6..11 from level 5 (126 pools, tiny).
__global__ __launch_bounds__(512) void build_high() {
    int bh = blockIdx.x;
    int warp = threadIdx.x >> 5, lane = threadIdx.x & 31;
    size_t base = (size_t)bh * HI_NODES * DD;

    int off_prev = 0, off = 128, cnt = 64;
#pragma unroll
    for (int l = 6; l <= 11; l++) {
        for (int j = warp; j < cnt; j += 16)
            poolp(g_hiK + base + (size_t)(off_prev + 2 * j) * DD,
                  g_hiK + base + (size_t)(off_prev + 2 * j + 1) * DD,
                  g_hiV + base + (size_t)(off_prev + 2 * j) * DD,
                  g_hiV + base + (size_t)(off_prev + 2 * j + 1) * DD,
                  g_hiK + base + (size_t)(off + j) * DD,
                  g_hiV + base + (size_t)(off + j) * DD, lane);
        __syncthreads();
        off_prev = off;
        off += cnt;
        cnt >>= 1;
    }
}

// Pass 3: fused attention. Block per 32-leaf chunk: rebuild levels 1..4 in
// smem, pull the (block-uniform) attended level-5..11 nodes from global, then
// warp-per-query batched softmax over all 13 candidate keys at once.
__global__ __launch_bounds__(256) void attn(const float* __restrict__ q,
                                            const float* __restrict__ k,
                                            const float* __restrict__ v,
                                            float* __restrict__ out) {
    __shared__ float smK[NROWS * DD], smV[NROWS * DD];
    int blk = blockIdx.x;
    int cc  = blk & (CPB - 1);
    int bh  = blk >> 7;
    int b = bh >> 3, h = bh & 7;
    int tid = threadIdx.x, warp = tid >> 5, lane = tid & 31;

    size_t rowbase = ((size_t)(b * SS + cc * CH) * HH + h) * DD;
    const float4* k4 = (const float4*)(k + rowbase);
    const float4* v4 = (const float4*)(v + rowbase);
#pragma unroll
    for (int i = tid; i < CH * 16; i += 256) {
        int r = i >> 4, c = i & 15;
        ((float4*)smK)[i] = k4[r * (HD / 4) + c];
        ((float4*)smV)[i] = v4[r * (HD / 4) + c];
    }
    // hi nodes: slot j attends level (5+j) node (cc>>j)-1, block-uniform
    if (warp < 7) {
        const int hioff[7] = {0, 128, 192, 224, 240, 248, 252};
        int n = cc >> warp;
        int node = (n > 0) ? n - 1 : 0;   // clamped; unused when invalid
        size_t o = ((size_t)bh * HI_NODES + hioff[warp] + node) * DD + 2 * lane;
        *(float2*)(smK + (R_HI + warp) * DD + 2 * lane) = *(const float2*)(g_hiK + o);
        *(float2*)(smV + (R_HI + warp) * DD + 2 * lane) = *(const float2*)(g_hiV + o);
    }
    __syncthreads();

    build_chunk_tree(smK, smV, warp, lane);

    // ---- attention: 4 queries per warp ----
    const int toff[4] = {R_TREE1, R_TREE2, R_TREE3, R_TREE4};
#pragma unroll
    for (int qi = 0; qi < 4; qi++) {
        int s_loc = warp * 4 + qi;
        int s = cc * CH + s_loc;
        size_t qoff = ((size_t)(b * SS + s) * HH + h) * DD + 2 * lane;
        float2 qv = *(const float2*)(q + qoff);

        // 13 candidate rows (smem row ids) + validity
        int  row[13];
        bool val[13];
        row[0] = s_loc;                         val[0] = true;           // self
        row[1] = (s_loc > 0) ? s_loc - 1 : 0;   val[1] = (s_loc & 1);    // sibling
#pragma unroll
        for (int l = 1; l <= 4; l++) {
            int n = s_loc >> l;
            row[1 + l] = toff[l - 1] + ((n > 0) ? n - 1 : 0);
            val[1 + l] = (n & 1);
        }
#pragma unroll
        for (int j = 0; j < 7; j++) {
            row[6 + j] = R_HI + j;
            val[6 + j] = ((cc >> j) & 1);
        }

        // partial dots + cache V
        float  pd[13];
        float2 vv[13];
#pragma unroll
        for (int i = 0; i < 13; i++) {
            float2 kk = *(const float2*)(smK + row[i] * DD + 2 * lane);
            vv[i]     = *(const float2*)(smV + row[i] * DD + 2 * lane);
            pd[i] = qv.x * kk.x + qv.y * kk.y;
        }
        // one butterfly reduces all 13 dots (independent chains pipeline)
#pragma unroll
        for (int o = 16; o; o >>= 1) {
#pragma unroll
            for (int i = 0; i < 13; i++)
                pd[i] += __shfl_xor_sync(0xffffffffu, pd[i], o);
        }
        // softmax over valid slots
        float m = -1e30f;
#pragma unroll
        for (int i = 0; i < 13; i++) {
            pd[i] = val[i] ? pd[i] * SCALE : -1e30f;
            m = fmaxf(m, pd[i]);
        }
        float denom = 0.0f;
        float2 acc; acc.x = 0.0f; acc.y = 0.0f;
#pragma unroll
        for (int i = 0; i < 13; i++) {
            float e = __expf(pd[i] - m);
            denom += e;
            acc.x += e * vv[i].x;
            acc.y += e * vv[i].y;
        }
        float inv = 1.0f / denom;
        float2 o2; o2.x = acc.x * inv; o2.y = acc.y * inv;
        *(float2*)(out + qoff) = o2;
    }
}

extern "C" void kernel_launch(void* const* d_in, const int* in_sizes, int n_in,
                              void* d_out, int out_size) {
    const float* q = (const float*)d_in[0];
    const float* k = (const float*)d_in[1];
    const float* v = (const float*)d_in[2];
    float* out = (float*)d_out;

    build5<<<NBH * CPB, 256>>>(k, v);
    build_high<<<NBH, 512>>>();
    attn<<<NBH * CPB, 256>>>(q, k, v, out);
}

// round 3
// speedup vs baseline: 1.4449x; 1.4449x over previous
#include <cuda_runtime.h>
#include <math.h>

#define BB 4
#define SS 4096
#define HH 8
#define DD 64
#define HD (HH*DD)
#define SCALE 0.125f
#define NBH (BB*HH)          // 32 (b,h) pairs
#define CH 32                // leaves per chunk
#define CPB (SS/CH)          // 128 chunks per bh
#define HI_NODES 254         // levels 5..11 per bh

// Global storage for tree levels 5..11 only (~2MB each, L2-resident).
// Per-bh layout: level (5+j) base = 256 - (256>>j):
//   l5 @0 (128), l6 @128, l7 @192, l8 @224, l9 @240, l10 @248, l11 @252.
__device__ float g_hiK[(size_t)NBH * HI_NODES * DD];
__device__ float g_hiV[(size_t)NBH * HI_NODES * DD];

__device__ __forceinline__ int hioff(int j) { return 256 - (256 >> j); }

// ---------- 8-lane-group softmax pool ----------
// Lane `sub` (0..7) owns dims {4*sub..4*sub+3} and {32+4*sub..32+4*sub+3}.
// mask = active lanes of the calling context (xor offsets 4,2,1 stay in-group).
__device__ __forceinline__ void pool8(const float* __restrict__ kc0,
                                      const float* __restrict__ kc1,
                                      const float* __restrict__ vc0,
                                      const float* __restrict__ vc1,
                                      float* __restrict__ kout,
                                      float* __restrict__ vout,
                                      int sub, unsigned mask) {
    float4 a0 = ((const float4*)kc0)[sub], a1 = ((const float4*)kc0)[sub + 8];
    float4 b0 = ((const float4*)kc1)[sub], b1 = ((const float4*)kc1)[sub + 8];
    float4 p0, p1;
    p0.x = 0.5f * (a0.x + b0.x); p0.y = 0.5f * (a0.y + b0.y);
    p0.z = 0.5f * (a0.z + b0.z); p0.w = 0.5f * (a0.w + b0.w);
    p1.x = 0.5f * (a1.x + b1.x); p1.y = 0.5f * (a1.y + b1.y);
    p1.z = 0.5f * (a1.z + b1.z); p1.w = 0.5f * (a1.w + b1.w);
    float ds = p0.x*p0.x + p0.y*p0.y + p0.z*p0.z + p0.w*p0.w
             + p1.x*p1.x + p1.y*p1.y + p1.z*p1.z + p1.w*p1.w;
    float d0 = p0.x*a0.x + p0.y*a0.y + p0.z*a0.z + p0.w*a0.w
             + p1.x*a1.x + p1.y*a1.y + p1.z*a1.z + p1.w*a1.w;
    float d1 = p0.x*b0.x + p0.y*b0.y + p0.z*b0.z + p0.w*b0.w
             + p1.x*b1.x + p1.y*b1.y + p1.z*b1.z + p1.w*b1.w;
#pragma unroll
    for (int o = 4; o; o >>= 1) {
        ds += __shfl_xor_sync(mask, ds, o);
        d0 += __shfl_xor_sync(mask, d0, o);
        d1 += __shfl_xor_sync(mask, d1, o);
    }
    float ss = ds * SCALE, s0 = d0 * SCALE, s1 = d1 * SCALE;
    float m  = fmaxf(ss, fmaxf(s0, s1));
    float es = __expf(ss - m), e0 = __expf(s0 - m), e1 = __expf(s1 - m);
    float inv = 1.0f / (es + e0 + e1 + 1e-9f);
    float hes = 0.5f * es;
    float4 va0 = ((const float4*)vc0)[sub], va1 = ((const float4*)vc0)[sub + 8];
    float4 vb0 = ((const float4*)vc1)[sub], vb1 = ((const float4*)vc1)[sub + 8];
    float4 o0, o1;
    o0.x = (hes*(va0.x+vb0.x) + e0*va0.x + e1*vb0.x) * inv;
    o0.y = (hes*(va0.y+vb0.y) + e0*va0.y + e1*vb0.y) * inv;
    o0.z = (hes*(va0.z+vb0.z) + e0*va0.z + e1*vb0.z) * inv;
    o0.w = (hes*(va0.w+vb0.w) + e0*va0.w + e1*vb0.w) * inv;
    o1.x = (hes*(va1.x+vb1.x) + e0*va1.x + e1*vb1.x) * inv;
    o1.y = (hes*(va1.y+vb1.y) + e0*va1.y + e1*vb1.y) * inv;
    o1.z = (hes*(va1.z+vb1.z) + e0*va1.z + e1*vb1.z) * inv;
    o1.w = (hes*(va1.w+vb1.w) + e0*va1.w + e1*vb1.w) * inv;
    ((float4*)kout)[sub] = p0;  ((float4*)kout)[sub + 8] = p1;
    ((float4*)vout)[sub] = o0;  ((float4*)vout)[sub + 8] = o1;
}

// Legacy warp-collective pool (full-dim per warp) for build_high only.
__device__ __forceinline__ void poolp(const float* __restrict__ kc0,
                                      const float* __restrict__ kc1,
                                      const float* __restrict__ vc0,
                                      const float* __restrict__ vc1,
                                      float* __restrict__ kout,
                                      float* __restrict__ vout, int lane) {
    float2 a  = *(const float2*)(kc0 + 2 * lane);
    float2 b  = *(const float2*)(kc1 + 2 * lane);
    float2 va = *(const float2*)(vc0 + 2 * lane);
    float2 vb = *(const float2*)(vc1 + 2 * lane);
    float2 kp;
    kp.x = 0.5f * (a.x + b.x);
    kp.y = 0.5f * (a.y + b.y);
    float ds = kp.x * kp.x + kp.y * kp.y;
    float d0 = kp.x * a.x + kp.y * a.y;
    float d1 = kp.x * b.x + kp.y * b.y;
#pragma unroll
    for (int o = 16; o; o >>= 1) {
        ds += __shfl_xor_sync(0xffffffffu, ds, o);
        d0 += __shfl_xor_sync(0xffffffffu, d0, o);
        d1 += __shfl_xor_sync(0xffffffffu, d1, o);
    }
    float ss = ds * SCALE, s0 = d0 * SCALE, s1 = d1 * SCALE;
    float m  = fmaxf(ss, fmaxf(s0, s1));
    float es = __expf(ss - m), e0 = __expf(s0 - m), e1 = __expf(s1 - m);
    float inv = 1.0f / (es + e0 + e1 + 1e-9f);
    float hes = 0.5f * es;
    float2 vp;
    vp.x = (hes * (va.x + vb.x) + e0 * va.x + e1 * vb.x) * inv;
    vp.y = (hes * (va.y + vb.y) + e0 * va.y + e1 * vb.y) * inv;
    *(float2*)(kout + 2 * lane) = kp;
    *(float2*)(vout + 2 * lane) = vp;
}

// Smem tree rows: L1 0-15, L2 16-23, L3 24-27, L4 28-29, HI 30-36 (attn only)
#define R_L2 16
#define R_L3 24
#define R_L4 28
#define R_HI 30

// Pass 1: per 32-leaf chunk, build levels 1..4 in smem, emit level-5 node.
__global__ __launch_bounds__(128) void build5(const float* __restrict__ k,
                                              const float* __restrict__ v) {
    __shared__ float sK[30 * DD], sV[30 * DD];
    int blk = blockIdx.x;            // bh*CPB + cc
    int cc  = blk & (CPB - 1);
    int bh  = blk >> 7;
    int b = bh >> 3, h = bh & 7;
    int tid = threadIdx.x, warp = tid >> 5, lane = tid & 31;
    int g = lane >> 3, sub = lane & 7;
    int slot = warp * 4 + g;         // 0..15

    const float* leafK = k + ((size_t)(b * SS + cc * CH) * HH + h) * DD;
    const float* leafV = v + ((size_t)(b * SS + cc * CH) * HH + h) * DD;

    // L1: 16 pools straight from global
    pool8(leafK + (size_t)(2 * slot) * HD, leafK + (size_t)(2 * slot + 1) * HD,
          leafV + (size_t)(2 * slot) * HD, leafV + (size_t)(2 * slot + 1) * HD,
          sK + slot * DD, sV + slot * DD, sub, 0xffffffffu);
    __syncthreads();
    if (slot < 8)
        pool8(sK + (2 * slot) * DD, sK + (2 * slot + 1) * DD,
              sV + (2 * slot) * DD, sV + (2 * slot + 1) * DD,
              sK + (R_L2 + slot) * DD, sV + (R_L2 + slot) * DD, sub, 0xffffffffu);
    __syncthreads();
    if (warp == 0) {
        pool8(sK + (R_L2 + 2 * g) * DD, sK + (R_L2 + 2 * g + 1) * DD,
              sV + (R_L2 + 2 * g) * DD, sV + (R_L2 + 2 * g + 1) * DD,
              sK + (R_L3 + g) * DD, sV + (R_L3 + g) * DD, sub, 0xffffffffu);
        __syncwarp();
        if (g < 2)
            pool8(sK + (R_L3 + 2 * g) * DD, sK + (R_L3 + 2 * g + 1) * DD,
                  sV + (R_L3 + 2 * g) * DD, sV + (R_L3 + 2 * g + 1) * DD,
                  sK + (R_L4 + g) * DD, sV + (R_L4 + g) * DD, sub, 0xffffu);
        __syncwarp();
        if (g == 0) {
            size_t o = ((size_t)bh * HI_NODES + cc) * DD;
            pool8(sK + R_L4 * DD, sK + (R_L4 + 1) * DD,
                  sV + R_L4 * DD, sV + (R_L4 + 1) * DD,
                  g_hiK + o, g_hiV + o, sub, 0xffu);
        }
    }
}

// Pass 2: per bh, build levels 6..11 from level 5 (126 pools, tiny).
__global__ __launch_bounds__(512) void build_high() {
    int bh = blockIdx.x;
    int warp = threadIdx.x >> 5, lane = threadIdx.x & 31;
    size_t base = (size_t)bh * HI_NODES * DD;

    int off_prev = 0, off = 128, cnt = 64;
#pragma unroll
    for (int l = 6; l <= 11; l++) {
        for (int j = warp; j < cnt; j += 16)
            poolp(g_hiK + base + (size_t)(off_prev + 2 * j) * DD,
                  g_hiK + base + (size_t)(off_prev + 2 * j + 1) * DD,
                  g_hiV + base + (size_t)(off_prev + 2 * j) * DD,
                  g_hiV + base + (size_t)(off_prev + 2 * j + 1) * DD,
                  g_hiK + base + (size_t)(off + j) * DD,
                  g_hiV + base + (size_t)(off + j) * DD, lane);
        __syncthreads();
        off_prev = off;
        off += cnt;
        cnt >>= 1;
    }
}

// Pass 3: fused attention, 8-lane group per query.
__global__ __launch_bounds__(256) void attn(const float* __restrict__ q,
                                            const float* __restrict__ k,
                                            const float* __restrict__ v,
                                            float* __restrict__ out) {
    __shared__ float sK[37 * DD], sV[37 * DD];
    int blk = blockIdx.x;
    int cc  = blk & (CPB - 1);
    int bh  = blk >> 7;
    int b = bh >> 3, h = bh & 7;
    int tid = threadIdx.x, warp = tid >> 5, lane = tid & 31;
    int g = lane >> 3, sub = lane & 7;
    int qid = tid >> 3;              // 0..31: query s_loc

    const float* leafK = k + ((size_t)(b * SS + cc * CH) * HH + h) * DD;
    const float* leafV = v + ((size_t)(b * SS + cc * CH) * HH + h) * DD;

    // prefetch q for my query
    size_t qoff = ((size_t)(b * SS + cc * CH + qid) * HH + h) * DD;
    float4 q0 = ((const float4*)(q + qoff))[sub];
    float4 q1 = ((const float4*)(q + qoff))[sub + 8];

    if (warp < 4) {
        // L1: 16 pools from global leaves
        int slot = warp * 4 + g;
        pool8(leafK + (size_t)(2 * slot) * HD, leafK + (size_t)(2 * slot + 1) * HD,
              leafV + (size_t)(2 * slot) * HD, leafV + (size_t)(2 * slot + 1) * HD,
              sK + slot * DD, sV + slot * DD, sub, 0xffffffffu);
    } else {
        // prefetch the 7 block-uniform hi nodes into smem rows 30..36
        int j = (warp - 4) * 4 + g;
        if (j < 7) {
            int n = cc >> j;
            int node = (n > 0) ? n - 1 : 0;
            const float* hk = g_hiK + ((size_t)bh * HI_NODES + hioff(j) + node) * DD;
            const float* hv = g_hiV + ((size_t)bh * HI_NODES + hioff(j) + node) * DD;
            ((float4*)(sK + (R_HI + j) * DD))[sub]     = ((const float4*)hk)[sub];
            ((float4*)(sK + (R_HI + j) * DD))[sub + 8] = ((const float4*)hk)[sub + 8];
            ((float4*)(sV + (R_HI + j) * DD))[sub]     = ((const float4*)hv)[sub];
            ((float4*)(sV + (R_HI + j) * DD))[sub + 8] = ((const float4*)hv)[sub + 8];
        }
    }
    __syncthreads();
    {
        int slot = warp * 4 + g;
        if (slot < 8)
            pool8(sK + (2 * slot) * DD, sK + (2 * slot + 1) * DD,
                  sV + (2 * slot) * DD, sV + (2 * slot + 1) * DD,
                  sK + (R_L2 + slot) * DD, sV + (R_L2 + slot) * DD, sub, 0xffffffffu);
    }
    __syncthreads();
    if (warp == 0) {
        pool8(sK + (R_L2 + 2 * g) * DD, sK + (R_L2 + 2 * g + 1) * DD,
              sV + (R_L2 + 2 * g) * DD, sV + (R_L2 + 2 * g + 1) * DD,
              sK + (R_L3 + g) * DD, sV + (R_L3 + g) * DD, sub, 0xffffffffu);
        __syncwarp();
        if (g < 2)
            pool8(sK + (R_L3 + 2 * g) * DD, sK + (R_L3 + 2 * g + 1) * DD,
                  sV + (R_L3 + 2 * g) * DD, sV + (R_L3 + 2 * g + 1) * DD,
                  sK + (R_L4 + g) * DD, sV + (R_L4 + g) * DD, sub, 0xffffu);
    }
    __syncthreads();

    // ---- batched 13-key attention for query qid ----
    int s_loc = qid;
    // K source pointers (row base) per slot
    const float* kp[13];
    const float* vp[13];
    bool val[13];
    kp[0] = leafK + (size_t)s_loc * HD;
    vp[0] = leafV + (size_t)s_loc * HD;
    val[0] = true;
    {
        int r = (s_loc > 0) ? s_loc - 1 : 0;
        kp[1] = leafK + (size_t)r * HD;
        vp[1] = leafV + (size_t)r * HD;
        val[1] = (s_loc & 1);
    }
    const int tbase[4] = {0, R_L2, R_L3, R_L4};
#pragma unroll
    for (int l = 1; l <= 4; l++) {
        int n = s_loc >> l;
        int row = tbase[l - 1] + ((n > 0) ? n - 1 : 0);
        kp[1 + l] = sK + row * DD;
        vp[1 + l] = sV + row * DD;
        val[1 + l] = (n & 1);
    }
#pragma unroll
    for (int j = 0; j < 7; j++) {
        kp[6 + j] = sK + (R_HI + j) * DD;
        vp[6 + j] = sV + (R_HI + j) * DD;
        val[6 + j] = ((cc >> j) & 1);
    }

    // K pass: partial dots
    float pd[13];
#pragma unroll
    for (int i = 0; i < 13; i++) {
        float4 x0 = ((const float4*)kp[i])[sub];
        float4 x1 = ((const float4*)kp[i])[sub + 8];
        pd[i] = q0.x*x0.x + q0.y*x0.y + q0.z*x0.z + q0.w*x0.w
              + q1.x*x1.x + q1.y*x1.y + q1.z*x1.z + q1.w*x1.w;
    }
    // 3-stage butterfly over the 8-lane group, all 13 chains in flight
#pragma unroll
    for (int o = 4; o; o >>= 1) {
#pragma unroll
        for (int i = 0; i < 13; i++)
            pd[i] += __shfl_xor_sync(0xffffffffu, pd[i], o);
    }
    float m = -1e30f;
#pragma unroll
    for (int i = 0; i < 13; i++) {
        pd[i] = val[i] ? pd[i] * SCALE : -1e30f;
        m = fmaxf(m, pd[i]);
    }
    float denom = 0.0f;
#pragma unroll
    for (int i = 0; i < 13; i++) {
        pd[i] = __expf(pd[i] - m);
        denom += pd[i];
    }
    // V pass
    float4 a0 = {0.f, 0.f, 0.f, 0.f}, a1 = {0.f, 0.f, 0.f, 0.f};
#pragma unroll
    for (int i = 0; i < 13; i++) {
        float4 y0 = ((const float4*)vp[i])[sub];
        float4 y1 = ((const float4*)vp[i])[sub + 8];
        float w = pd[i];
        a0.x += w * y0.x; a0.y += w * y0.y; a0.z += w * y0.z; a0.w += w * y0.w;
        a1.x += w * y1.x; a1.y += w * y1.y; a1.z += w * y1.z; a1.w += w * y1.w;
    }
    float inv = 1.0f / denom;
    a0.x *= inv; a0.y *= inv; a0.z *= inv; a0.w *= inv;
    a1.x *= inv; a1.y *= inv; a1.z *= inv; a1.w *= inv;
    ((float4*)(out + qoff))[sub]     = a0;
    ((float4*)(out + qoff))[sub + 8] = a1;
}

extern "C" void kernel_launch(void* const* d_in, const int* in_sizes, int n_in,
                              void* d_out, int out_size) {
    const float* q = (const float*)d_in[0];
    const float* k = (const float*)d_in[1];
    const float* v = (const float*)d_in[2];
    float* out = (float*)d_out;

    build5<<<NBH * CPB, 128>>>(k, v);
    build_high<<<NBH, 512>>>();
    attn<<<NBH * CPB, 256>>>(q, k, v, out);
}

// round 4
// speedup vs baseline: 1.4802x; 1.0244x over previous
#include <cuda_runtime.h>
#include <math.h>

#define BB 4
#define SS 4096
#define HH 8
#define DD 64
#define HD (HH*DD)
#define SCALE 0.125f
#define NBH (BB*HH)          // 32 (b,h) pairs
#define CH 32                // leaves per chunk
#define CPB (SS/CH)          // 128 chunks per bh
#define HI_NODES 254         // levels 5..11 per bh

// Global storage for tree levels 5..11 only (~2MB each, L2-resident).
__device__ float g_hiK[(size_t)NBH * HI_NODES * DD];
__device__ float g_hiV[(size_t)NBH * HI_NODES * DD];

__device__ __forceinline__ int hioff(int j) { return 256 - (256 >> j); }

// ---------- 8-lane-group softmax pool ----------
// Lane `sub` (0..7) owns dims {4*sub..} and {32+4*sub..}. mask = 0xFF<<(8*g).
__device__ __forceinline__ void pool8(const float* __restrict__ kc0,
                                      const float* __restrict__ kc1,
                                      const float* __restrict__ vc0,
                                      const float* __restrict__ vc1,
                                      float* __restrict__ kout,
                                      float* __restrict__ vout,
                                      int sub, unsigned mask) {
    float4 a0 = ((const float4*)kc0)[sub], a1 = ((const float4*)kc0)[sub + 8];
    float4 b0 = ((const float4*)kc1)[sub], b1 = ((const float4*)kc1)[sub + 8];
    float4 p0, p1;
    p0.x = 0.5f * (a0.x + b0.x); p0.y = 0.5f * (a0.y + b0.y);
    p0.z = 0.5f * (a0.z + b0.z); p0.w = 0.5f * (a0.w + b0.w);
    p1.x = 0.5f * (a1.x + b1.x); p1.y = 0.5f * (a1.y + b1.y);
    p1.z = 0.5f * (a1.z + b1.z); p1.w = 0.5f * (a1.w + b1.w);
    float ds = p0.x*p0.x + p0.y*p0.y + p0.z*p0.z + p0.w*p0.w
             + p1.x*p1.x + p1.y*p1.y + p1.z*p1.z + p1.w*p1.w;
    float d0 = p0.x*a0.x + p0.y*a0.y + p0.z*a0.z + p0.w*a0.w
             + p1.x*a1.x + p1.y*a1.y + p1.z*a1.z + p1.w*a1.w;
    float d1 = p0.x*b0.x + p0.y*b0.y + p0.z*b0.z + p0.w*b0.w
             + p1.x*b1.x + p1.y*b1.y + p1.z*b1.z + p1.w*b1.w;
#pragma unroll
    for (int o = 4; o; o >>= 1) {
        ds += __shfl_xor_sync(mask, ds, o);
        d0 += __shfl_xor_sync(mask, d0, o);
        d1 += __shfl_xor_sync(mask, d1, o);
    }
    float ss = ds * SCALE, s0 = d0 * SCALE, s1 = d1 * SCALE;
    float m  = fmaxf(ss, fmaxf(s0, s1));
    float es = __expf(ss - m), e0 = __expf(s0 - m), e1 = __expf(s1 - m);
    float inv = 1.0f / (es + e0 + e1 + 1e-9f);
    float hes = 0.5f * es;
    float4 va0 = ((const float4*)vc0)[sub], va1 = ((const float4*)vc0)[sub + 8];
    float4 vb0 = ((const float4*)vc1)[sub], vb1 = ((const float4*)vc1)[sub + 8];
    float4 o0, o1;
    o0.x = (hes*(va0.x+vb0.x) + e0*va0.x + e1*vb0.x) * inv;
    o0.y = (hes*(va0.y+vb0.y) + e0*va0.y + e1*vb0.y) * inv;
    o0.z = (hes*(va0.z+vb0.z) + e0*va0.z + e1*vb0.z) * inv;
    o0.w = (hes*(va0.w+vb0.w) + e0*va0.w + e1*vb0.w) * inv;
    o1.x = (hes*(va1.x+vb1.x) + e0*va1.x + e1*vb1.x) * inv;
    o1.y = (hes*(va1.y+vb1.y) + e0*va1.y + e1*vb1.y) * inv;
    o1.z = (hes*(va1.z+vb1.z) + e0*va1.z + e1*vb1.z) * inv;
    o1.w = (hes*(va1.w+vb1.w) + e0*va1.w + e1*vb1.w) * inv;
    ((float4*)kout)[sub] = p0;  ((float4*)kout)[sub + 8] = p1;
    ((float4*)vout)[sub] = o0;  ((float4*)vout)[sub + 8] = o1;
}

// Warp-collective full-dim pool for build_high only.
__device__ __forceinline__ void poolp(const float* __restrict__ kc0,
                                      const float* __restrict__ kc1,
                                      const float* __restrict__ vc0,
                                      const float* __restrict__ vc1,
                                      float* __restrict__ kout,
                                      float* __restrict__ vout, int lane) {
    float2 a  = *(const float2*)(kc0 + 2 * lane);
    float2 b  = *(const float2*)(kc1 + 2 * lane);
    float2 va = *(const float2*)(vc0 + 2 * lane);
    float2 vb = *(const float2*)(vc1 + 2 * lane);
    float2 kp;
    kp.x = 0.5f * (a.x + b.x);
    kp.y = 0.5f * (a.y + b.y);
    float ds = kp.x * kp.x + kp.y * kp.y;
    float d0 = kp.x * a.x + kp.y * a.y;
    float d1 = kp.x * b.x + kp.y * b.y;
#pragma unroll
    for (int o = 16; o; o >>= 1) {
        ds += __shfl_xor_sync(0xffffffffu, ds, o);
        d0 += __shfl_xor_sync(0xffffffffu, d0, o);
        d1 += __shfl_xor_sync(0xffffffffu, d1, o);
    }
    float ss = ds * SCALE, s0 = d0 * SCALE, s1 = d1 * SCALE;
    float m  = fmaxf(ss, fmaxf(s0, s1));
    float es = __expf(ss - m), e0 = __expf(s0 - m), e1 = __expf(s1 - m);
    float inv = 1.0f / (es + e0 + e1 + 1e-9f);
    float hes = 0.5f * es;
    float2 vp;
    vp.x = (hes * (va.x + vb.x) + e0 * va.x + e1 * vb.x) * inv;
    vp.y = (hes * (va.y + vb.y) + e0 * va.y + e1 * vb.y) * inv;
    *(float2*)(kout + 2 * lane) = kp;
    *(float2*)(vout + 2 * lane) = vp;
}

// ---------- Pass 1: two 32-leaf chunks per block; emit level-5 nodes ----------
// Per-team smem rows: L1 0-15, L2 16-23, L3 24-27, L4 28-29  (30 rows/team)
__global__ __launch_bounds__(256) void build5(const float* __restrict__ k,
                                              const float* __restrict__ v) {
    __shared__ float sK[60 * DD], sV[60 * DD];
    int tid = threadIdx.x, warp = tid >> 5, lane = tid & 31;
    int team = warp >> 2, w = warp & 3;
    int g = lane >> 3, sub = lane & 7;
    unsigned gmask = 0xFFu << (g * 8);
    int slot = w * 4 + g;            // 0..15 within team

    int blk = blockIdx.x;            // covers 2 chunks
    int cc  = (blk * 2 + team) & (CPB - 1);
    int bh  = (blk * 2 + team) >> 7;
    int b = bh >> 3, h = bh & 7;

    float* tK = sK + team * 30 * DD;
    float* tV = sV + team * 30 * DD;
    const float* leafK = k + ((size_t)(b * SS + cc * CH) * HH + h) * DD;
    const float* leafV = v + ((size_t)(b * SS + cc * CH) * HH + h) * DD;

    // L1: 16 pools straight from global
    pool8(leafK + (size_t)(2 * slot) * HD, leafK + (size_t)(2 * slot + 1) * HD,
          leafV + (size_t)(2 * slot) * HD, leafV + (size_t)(2 * slot + 1) * HD,
          tK + slot * DD, tV + slot * DD, sub, gmask);
    __syncthreads();
    if (w < 2)   // slots 0..7
        pool8(tK + (2 * slot) * DD, tK + (2 * slot + 1) * DD,
              tV + (2 * slot) * DD, tV + (2 * slot + 1) * DD,
              tK + (16 + slot) * DD, tV + (16 + slot) * DD, sub, gmask);
    __syncthreads();
    if (w == 0) {
        pool8(tK + (16 + 2 * g) * DD, tK + (16 + 2 * g + 1) * DD,
              tV + (16 + 2 * g) * DD, tV + (16 + 2 * g + 1) * DD,
              tK + (24 + g) * DD, tV + (24 + g) * DD, sub, gmask);
        __syncwarp();
        if (g < 2)
            pool8(tK + (24 + 2 * g) * DD, tK + (24 + 2 * g + 1) * DD,
                  tV + (24 + 2 * g) * DD, tV + (24 + 2 * g + 1) * DD,
                  tK + (28 + g) * DD, tV + (28 + g) * DD, sub, gmask);
        __syncwarp();
        if (g == 0) {
            size_t o = ((size_t)bh * HI_NODES + cc) * DD;
            pool8(tK + 28 * DD, tK + 29 * DD, tV + 28 * DD, tV + 29 * DD,
                  g_hiK + o, g_hiV + o, sub, 0xFFu);
        }
    }
}

// ---------- Pass 2: per bh, levels 6..11 (126 pools, tiny) ----------
__global__ __launch_bounds__(512) void build_high() {
    int bh = blockIdx.x;
    int warp = threadIdx.x >> 5, lane = threadIdx.x & 31;
    size_t base = (size_t)bh * HI_NODES * DD;

    int off_prev = 0, off = 128, cnt = 64;
#pragma unroll
    for (int l = 6; l <= 11; l++) {
        for (int j = warp; j < cnt; j += 16)
            poolp(g_hiK + base + (size_t)(off_prev + 2 * j) * DD,
                  g_hiK + base + (size_t)(off_prev + 2 * j + 1) * DD,
                  g_hiV + base + (size_t)(off_prev + 2 * j) * DD,
                  g_hiV + base + (size_t)(off_prev + 2 * j + 1) * DD,
                  g_hiK + base + (size_t)(off + j) * DD,
                  g_hiV + base + (size_t)(off + j) * DD, lane);
        __syncthreads();
        off_prev = off;
        off += cnt;
        cnt >>= 1;
    }
}

// ---------- Pass 3: fused attention, all candidate rows in smem ----------
// Smem rows: leaves 0..31, L1 32..47, L2 48..55, L3 56..59, L4 60..61,
//            HI 62..68.  69 rows x 64 f x 2 arrays = 35.3 KB.
#define R_L1 32
#define R_L2 48
#define R_L3 56
#define R_L4 60
#define R_HI 62
__global__ __launch_bounds__(256) void attn(const float* __restrict__ q,
                                            const float* __restrict__ k,
                                            const float* __restrict__ v,
                                            float* __restrict__ out) {
    __shared__ float sK[69 * DD], sV[69 * DD];
    int blk = blockIdx.x;
    int cc  = blk & (CPB - 1);
    int bh  = blk >> 7;
    int b = bh >> 3, h = bh & 7;
    int tid = threadIdx.x, warp = tid >> 5, lane = tid & 31;
    int g = lane >> 3, sub = lane & 7;
    unsigned gmask = 0xFFu << (g * 8);
    int qid = tid >> 3;              // 0..31 query s_loc (one per 8-lane group)

    const float* leafK = k + ((size_t)(b * SS + cc * CH) * HH + h) * DD;
    const float* leafV = v + ((size_t)(b * SS + cc * CH) * HH + h) * DD;

    // stage leaves: 512 float4 per tensor, 2 per thread, coalesced
#pragma unroll
    for (int i = tid; i < 512; i += 256) {
        int r = i >> 4, c = i & 15;
        ((float4*)sK)[r * 16 + c] = ((const float4*)(leafK + (size_t)r * HD))[c];
        ((float4*)sV)[r * 16 + c] = ((const float4*)(leafV + (size_t)r * HD))[c];
    }
    // stage 7 block-uniform hi rows (112 float4 per tensor)
    if (tid < 112) {
        int j = tid >> 4, c = tid & 15;
        int n = cc >> j;
        int node = (n > 0) ? n - 1 : 0;
        size_t o = ((size_t)bh * HI_NODES + hioff(j) + node) * DD;
        ((float4*)(sK + (R_HI + j) * DD))[c] = ((const float4*)(g_hiK + o))[c];
        ((float4*)(sV + (R_HI + j) * DD))[c] = ((const float4*)(g_hiV + o))[c];
    }
    // q into registers
    size_t qoff = ((size_t)(b * SS + cc * CH + qid) * HH + h) * DD;
    float4 q0 = ((const float4*)(q + qoff))[sub];
    float4 q1 = ((const float4*)(q + qoff))[sub + 8];
    __syncthreads();

    // tree build from smem leaves
    if (warp < 4) {
        int slot = warp * 4 + g;     // 0..15
        pool8(sK + (2 * slot) * DD, sK + (2 * slot + 1) * DD,
              sV + (2 * slot) * DD, sV + (2 * slot + 1) * DD,
              sK + (R_L1 + slot) * DD, sV + (R_L1 + slot) * DD, sub, gmask);
    }
    __syncthreads();
    if (warp < 2) {
        int slot = warp * 4 + g;     // 0..7
        pool8(sK + (R_L1 + 2 * slot) * DD, sK + (R_L1 + 2 * slot + 1) * DD,
              sV + (R_L1 + 2 * slot) * DD, sV + (R_L1 + 2 * slot + 1) * DD,
              sK + (R_L2 + slot) * DD, sV + (R_L2 + slot) * DD, sub, gmask);
    }
    __syncthreads();
    if (warp == 0) {
        pool8(sK + (R_L2 + 2 * g) * DD, sK + (R_L2 + 2 * g + 1) * DD,
              sV + (R_L2 + 2 * g) * DD, sV + (R_L2 + 2 * g + 1) * DD,
              sK + (R_L3 + g) * DD, sV + (R_L3 + g) * DD, sub, gmask);
        __syncwarp();
        if (g < 2)
            pool8(sK + (R_L3 + 2 * g) * DD, sK + (R_L3 + 2 * g + 1) * DD,
                  sV + (R_L3 + 2 * g) * DD, sV + (R_L3 + 2 * g + 1) * DD,
                  sK + (R_L4 + g) * DD, sV + (R_L4 + g) * DD, sub, gmask);
    }
    __syncthreads();

    // ---- batched 13-key attention for query qid, smem row ids only ----
    int rows[13];
    bool val[13];
    rows[0] = qid;                        val[0] = true;
    rows[1] = (qid > 0) ? qid - 1 : 0;    val[1] = (qid & 1);
    const int tbase[4] = {R_L1, R_L2, R_L3, R_L4};
#pragma unroll
    for (int l = 1; l <= 4; l++) {
        int n = qid >> l;
        rows[1 + l] = tbase[l - 1] + ((n > 0) ? n - 1 : 0);
        val[1 + l]  = (n & 1);
    }
#pragma unroll
    for (int j = 0; j < 7; j++) {
        rows[6 + j] = R_HI + j;
        val[6 + j]  = ((cc >> j) & 1);
    }

    float pd[13];
#pragma unroll
    for (int i = 0; i < 13; i++) {
        const float4* kr = (const float4*)(sK + rows[i] * DD);
        float4 x0 = kr[sub], x1 = kr[sub + 8];
        pd[i] = q0.x*x0.x + q0.y*x0.y + q0.z*x0.z + q0.w*x0.w
              + q1.x*x1.x + q1.y*x1.y + q1.z*x1.z + q1.w*x1.w;
    }
#pragma unroll
    for (int o = 4; o; o >>= 1) {
#pragma unroll
        for (int i = 0; i < 13; i++)
            pd[i] += __shfl_xor_sync(0xffffffffu, pd[i], o);
    }
    float m = -1e30f;
#pragma unroll
    for (int i = 0; i < 13; i++) {
        pd[i] = val[i] ? pd[i] * SCALE : -1e30f;
        m = fmaxf(m, pd[i]);
    }
    float denom = 0.0f;
#pragma unroll
    for (int i = 0; i < 13; i++) {
        pd[i] = __expf(pd[i] - m);
        denom += pd[i];
    }
    float4 a0 = {0.f, 0.f, 0.f, 0.f}, a1 = {0.f, 0.f, 0.f, 0.f};
#pragma unroll
    for (int i = 0; i < 13; i++) {
        const float4* vr = (const float4*)(sV + rows[i] * DD);
        float4 y0 = vr[sub], y1 = vr[sub + 8];
        float w = pd[i];
        a0.x += w * y0.x; a0.y += w * y0.y; a0.z += w * y0.z; a0.w += w * y0.w;
        a1.x += w * y1.x; a1.y += w * y1.y; a1.z += w * y1.z; a1.w += w * y1.w;
    }
    float inv = 1.0f / denom;
    a0.x *= inv; a0.y *= inv; a0.z *= inv; a0.w *= inv;
    a1.x *= inv; a1.y *= inv; a1.z *= inv; a1.w *= inv;
    ((float4*)(out + qoff))[sub]     = a0;
    ((float4*)(out + qoff))[sub + 8] = a1;
}

extern "C" void kernel_launch(void* const* d_in, const int* in_sizes, int n_in,
                              void* d_out, int out_size) {
    const float* q = (const float*)d_in[0];
    const float* k = (const float*)d_in[1];
    const float* v = (const float*)d_in[2];
    float* out = (float*)d_out;

    build5<<<NBH * CPB / 2, 256>>>(k, v);
    build_high<<<NBH, 512>>>();
    attn<<<NBH * CPB, 256>>>(q, k, v, out);
}

// round 5
// speedup vs baseline: 1.5208x; 1.0274x over previous
#include <cuda_runtime.h>
#include <math.h>

#define BB 4
#define SS 4096
#define HH 8
#define DD 64
#define HD (HH*DD)
#define SCALE 0.125f
#define NBH (BB*HH)          // 32 (b,h) pairs
#define CH 32                // leaves per chunk
#define CPB (SS/CH)          // 128 chunks per bh
#define HI_NODES 254         // levels 5..11 per bh

// Global storage for tree levels 5..11 only (~2MB each, L2-resident).
__device__ float g_hiK[(size_t)NBH * HI_NODES * DD];
__device__ float g_hiV[(size_t)NBH * HI_NODES * DD];

__device__ __forceinline__ int hioff(int j) { return 256 - (256 >> j); }

// ---------- 8-lane-group softmax pool ----------
// Lane `sub` (0..7) owns dims {4*sub..} and {32+4*sub..}. mask = 0xFF<<(8*g).
__device__ __forceinline__ void pool8(const float* __restrict__ kc0,
                                      const float* __restrict__ kc1,
                                      const float* __restrict__ vc0,
                                      const float* __restrict__ vc1,
                                      float* __restrict__ kout,
                                      float* __restrict__ vout,
                                      int sub, unsigned mask) {
    float4 a0 = ((const float4*)kc0)[sub], a1 = ((const float4*)kc0)[sub + 8];
    float4 b0 = ((const float4*)kc1)[sub], b1 = ((const float4*)kc1)[sub + 8];
    float4 p0, p1;
    p0.x = 0.5f * (a0.x + b0.x); p0.y = 0.5f * (a0.y + b0.y);
    p0.z = 0.5f * (a0.z + b0.z); p0.w = 0.5f * (a0.w + b0.w);
    p1.x = 0.5f * (a1.x + b1.x); p1.y = 0.5f * (a1.y + b1.y);
    p1.z = 0.5f * (a1.z + b1.z); p1.w = 0.5f * (a1.w + b1.w);
    float ds = p0.x*p0.x + p0.y*p0.y + p0.z*p0.z + p0.w*p0.w
             + p1.x*p1.x + p1.y*p1.y + p1.z*p1.z + p1.w*p1.w;
    float d0 = p0.x*a0.x + p0.y*a0.y + p0.z*a0.z + p0.w*a0.w
             + p1.x*a1.x + p1.y*a1.y + p1.z*a1.z + p1.w*a1.w;
    float d1 = p0.x*b0.x + p0.y*b0.y + p0.z*b0.z + p0.w*b0.w
             + p1.x*b1.x + p1.y*b1.y + p1.z*b1.z + p1.w*b1.w;
#pragma unroll
    for (int o = 4; o; o >>= 1) {
        ds += __shfl_xor_sync(mask, ds, o);
        d0 += __shfl_xor_sync(mask, d0, o);
        d1 += __shfl_xor_sync(mask, d1, o);
    }
    float ss = ds * SCALE, s0 = d0 * SCALE, s1 = d1 * SCALE;
    float m  = fmaxf(ss, fmaxf(s0, s1));
    float es = __expf(ss - m), e0 = __expf(s0 - m), e1 = __expf(s1 - m);
    float inv = 1.0f / (es + e0 + e1 + 1e-9f);
    float hes = 0.5f * es;
    float4 va0 = ((const float4*)vc0)[sub], va1 = ((const float4*)vc0)[sub + 8];
    float4 vb0 = ((const float4*)vc1)[sub], vb1 = ((const float4*)vc1)[sub + 8];
    float4 o0, o1;
    o0.x = (hes*(va0.x+vb0.x) + e0*va0.x + e1*vb0.x) * inv;
    o0.y = (hes*(va0.y+vb0.y) + e0*va0.y + e1*vb0.y) * inv;
    o0.z = (hes*(va0.z+vb0.z) + e0*va0.z + e1*vb0.z) * inv;
    o0.w = (hes*(va0.w+vb0.w) + e0*va0.w + e1*vb0.w) * inv;
    o1.x = (hes*(va1.x+vb1.x) + e0*va1.x + e1*vb1.x) * inv;
    o1.y = (hes*(va1.y+vb1.y) + e0*va1.y + e1*vb1.y) * inv;
    o1.z = (hes*(va1.z+vb1.z) + e0*va1.z + e1*vb1.z) * inv;
    o1.w = (hes*(va1.w+vb1.w) + e0*va1.w + e1*vb1.w) * inv;
    ((float4*)kout)[sub] = p0;  ((float4*)kout)[sub + 8] = p1;
    ((float4*)vout)[sub] = o0;  ((float4*)vout)[sub + 8] = o1;
}

// Warp-collective full-dim pool for build_high only.
__device__ __forceinline__ void poolp(const float* __restrict__ kc0,
                                      const float* __restrict__ kc1,
                                      const float* __restrict__ vc0,
                                      const float* __restrict__ vc1,
                                      float* __restrict__ kout,
                                      float* __restrict__ vout, int lane) {
    float2 a  = *(const float2*)(kc0 + 2 * lane);
    float2 b  = *(const float2*)(kc1 + 2 * lane);
    float2 va = *(const float2*)(vc0 + 2 * lane);
    float2 vb = *(const float2*)(vc1 + 2 * lane);
    float2 kp;
    kp.x = 0.5f * (a.x + b.x);
    kp.y = 0.5f * (a.y + b.y);
    float ds = kp.x * kp.x + kp.y * kp.y;
    float d0 = kp.x * a.x + kp.y * a.y;
    float d1 = kp.x * b.x + kp.y * b.y;
#pragma unroll
    for (int o = 16; o; o >>= 1) {
        ds += __shfl_xor_sync(0xffffffffu, ds, o);
        d0 += __shfl_xor_sync(0xffffffffu, d0, o);
        d1 += __shfl_xor_sync(0xffffffffu, d1, o);
    }
    float ss = ds * SCALE, s0 = d0 * SCALE, s1 = d1 * SCALE;
    float m  = fmaxf(ss, fmaxf(s0, s1));
    float es = __expf(ss - m), e0 = __expf(s0 - m), e1 = __expf(s1 - m);
    float inv = 1.0f / (es + e0 + e1 + 1e-9f);
    float hes = 0.5f * es;
    float2 vp;
    vp.x = (hes * (va.x + vb.x) + e0 * va.x + e1 * vb.x) * inv;
    vp.y = (hes * (va.y + vb.y) + e0 * va.y + e1 * vb.y) * inv;
    *(float2*)(kout + 2 * lane) = kp;
    *(float2*)(vout + 2 * lane) = vp;
}

// ---------- Pass 1 (R3 config): per 32-leaf chunk, emit level-5 node ----------
// Smem rows: L1 0-15, L2 16-23, L3 24-27, L4 28-29
__global__ __launch_bounds__(128) void build5(const float* __restrict__ k,
                                              const float* __restrict__ v) {
    __shared__ float sK[30 * DD], sV[30 * DD];
    int blk = blockIdx.x;            // bh*CPB + cc
    int cc  = blk & (CPB - 1);
    int bh  = blk >> 7;
    int b = bh >> 3, h = bh & 7;
    int tid = threadIdx.x, warp = tid >> 5, lane = tid & 31;
    int g = lane >> 3, sub = lane & 7;
    unsigned gmask = 0xFFu << (g * 8);
    int slot = warp * 4 + g;         // 0..15

    const float* leafK = k + ((size_t)(b * SS + cc * CH) * HH + h) * DD;
    const float* leafV = v + ((size_t)(b * SS + cc * CH) * HH + h) * DD;

    pool8(leafK + (size_t)(2 * slot) * HD, leafK + (size_t)(2 * slot + 1) * HD,
          leafV + (size_t)(2 * slot) * HD, leafV + (size_t)(2 * slot + 1) * HD,
          sK + slot * DD, sV + slot * DD, sub, gmask);
    __syncthreads();
    if (slot < 8)
        pool8(sK + (2 * slot) * DD, sK + (2 * slot + 1) * DD,
              sV + (2 * slot) * DD, sV + (2 * slot + 1) * DD,
              sK + (16 + slot) * DD, sV + (16 + slot) * DD, sub, gmask);
    __syncthreads();
    if (warp == 0) {
        pool8(sK + (16 + 2 * g) * DD, sK + (16 + 2 * g + 1) * DD,
              sV + (16 + 2 * g) * DD, sV + (16 + 2 * g + 1) * DD,
              sK + (24 + g) * DD, sV + (24 + g) * DD, sub, gmask);
        __syncwarp();
        if (g < 2)
            pool8(sK + (24 + 2 * g) * DD, sK + (24 + 2 * g + 1) * DD,
                  sV + (24 + 2 * g) * DD, sV + (24 + 2 * g + 1) * DD,
                  sK + (28 + g) * DD, sV + (28 + g) * DD, sub, gmask);
        __syncwarp();
        if (g == 0) {
            size_t o = ((size_t)bh * HI_NODES + cc) * DD;
            pool8(sK + 28 * DD, sK + 29 * DD, sV + 28 * DD, sV + 29 * DD,
                  g_hiK + o, g_hiV + o, sub, 0xFFu);
        }
    }
}

// ---------- Pass 2: per bh, levels 6..11 (126 pools, tiny) ----------
__global__ __launch_bounds__(512) void build_high() {
    int bh = blockIdx.x;
    int warp = threadIdx.x >> 5, lane = threadIdx.x & 31;
    size_t base = (size_t)bh * HI_NODES * DD;

    int off_prev = 0, off = 128, cnt = 64;
#pragma unroll
    for (int l = 6; l <= 11; l++) {
        for (int j = warp; j < cnt; j += 16)
            poolp(g_hiK + base + (size_t)(off_prev + 2 * j) * DD,
                  g_hiK + base + (size_t)(off_prev + 2 * j + 1) * DD,
                  g_hiV + base + (size_t)(off_prev + 2 * j) * DD,
                  g_hiV + base + (size_t)(off_prev + 2 * j + 1) * DD,
                  g_hiK + base + (size_t)(off + j) * DD,
                  g_hiV + base + (size_t)(off + j) * DD, lane);
        __syncthreads();
        off_prev = off;
        off += cnt;
        cnt >>= 1;
    }
}

// ---------- Pass 3: fused attention, tree-only smem (18.5 KB) ----------
// Smem rows: L1 0..15, L2 16..23, L3 24..27, L4 28..29, HI 30..36 (37 rows).
#define R_L2 16
#define R_L3 24
#define R_L4 28
#define R_HI 30
__global__ __launch_bounds__(256) void attn(const float* __restrict__ q,
                                            const float* __restrict__ k,
                                            const float* __restrict__ v,
                                            float* __restrict__ out) {
    __shared__ float sK[37 * DD], sV[37 * DD];
    int blk = blockIdx.x;
    int cc  = blk & (CPB - 1);
    int bh  = blk >> 7;
    int b = bh >> 3, h = bh & 7;
    int tid = threadIdx.x, warp = tid >> 5, lane = tid & 31;
    int g = lane >> 3, sub = lane & 7;
    unsigned gmask = 0xFFu << (g * 8);
    int qid = tid >> 3;              // 0..31 query s_loc (one per 8-lane group)

    const float* leafK = k + ((size_t)(b * SS + cc * CH) * HH + h) * DD;
    const float* leafV = v + ((size_t)(b * SS + cc * CH) * HH + h) * DD;

    // q into registers
    size_t qoff = ((size_t)(b * SS + cc * CH + qid) * HH + h) * DD;
    float4 q0 = ((const float4*)(q + qoff))[sub];
    float4 q1 = ((const float4*)(q + qoff))[sub + 8];

    if (warp < 4) {
        // L1: 16 pools straight from global leaves
        int slot = warp * 4 + g;
        pool8(leafK + (size_t)(2 * slot) * HD, leafK + (size_t)(2 * slot + 1) * HD,
              leafV + (size_t)(2 * slot) * HD, leafV + (size_t)(2 * slot + 1) * HD,
              sK + slot * DD, sV + slot * DD, sub, gmask);
    } else {
        // stage 7 block-uniform hi rows
        int j = (warp - 4) * 4 + g;
        if (j < 7) {
            int n = cc >> j;
            int node = (n > 0) ? n - 1 : 0;
            const float* hk = g_hiK + ((size_t)bh * HI_NODES + hioff(j) + node) * DD;
            const float* hv = g_hiV + ((size_t)bh * HI_NODES + hioff(j) + node) * DD;
            ((float4*)(sK + (R_HI + j) * DD))[sub]     = ((const float4*)hk)[sub];
            ((float4*)(sK + (R_HI + j) * DD))[sub + 8] = ((const float4*)hk)[sub + 8];
            ((float4*)(sV + (R_HI + j) * DD))[sub]     = ((const float4*)hv)[sub];
            ((float4*)(sV + (R_HI + j) * DD))[sub + 8] = ((const float4*)hv)[sub + 8];
        }
    }
    __syncthreads();
    if (warp < 2) {
        int slot = warp * 4 + g;     // 0..7
        pool8(sK + (2 * slot) * DD, sK + (2 * slot + 1) * DD,
              sV + (2 * slot) * DD, sV + (2 * slot + 1) * DD,
              sK + (R_L2 + slot) * DD, sV + (R_L2 + slot) * DD, sub, gmask);
    }
    __syncthreads();
    if (warp == 0) {
        pool8(sK + (R_L2 + 2 * g) * DD, sK + (R_L2 + 2 * g + 1) * DD,
              sV + (R_L2 + 2 * g) * DD, sV + (R_L2 + 2 * g + 1) * DD,
              sK + (R_L3 + g) * DD, sV + (R_L3 + g) * DD, sub, gmask);
        __syncwarp();
        if (g < 2)
            pool8(sK + (R_L3 + 2 * g) * DD, sK + (R_L3 + 2 * g + 1) * DD,
                  sV + (R_L3 + 2 * g) * DD, sV + (R_L3 + 2 * g + 1) * DD,
                  sK + (R_L4 + g) * DD, sV + (R_L4 + g) * DD, sub, gmask);
    }
    __syncthreads();

    // ---- batched 13-key attention for query qid ----
    // slots 0/1 (self, left-sibling leaf) read from GLOBAL (L1-hot);
    // slots 2..12 from smem tree rows.
    const float* selfK = leafK + (size_t)qid * HD;
    const float* selfV = leafV + (size_t)qid * HD;
    int sib = (qid > 0) ? qid - 1 : 0;
    const float* sibK = leafK + (size_t)sib * HD;
    const float* sibV = leafV + (size_t)sib * HD;

    int rows[11];
    bool val[13];
    val[0] = true;
    val[1] = (qid & 1);
    const int tbase[4] = {0, R_L2, R_L3, R_L4};
#pragma unroll
    for (int l = 1; l <= 4; l++) {
        int n = qid >> l;
        rows[l - 1] = tbase[l - 1] + ((n > 0) ? n - 1 : 0);
        val[1 + l]  = (n & 1);
    }
#pragma unroll
    for (int j = 0; j < 7; j++) {
        rows[4 + j] = R_HI + j;
        val[6 + j]  = ((cc >> j) & 1);
    }

    float pd[13];
    {
        float4 x0 = ((const float4*)selfK)[sub], x1 = ((const float4*)selfK)[sub + 8];
        pd[0] = q0.x*x0.x + q0.y*x0.y + q0.z*x0.z + q0.w*x0.w
              + q1.x*x1.x + q1.y*x1.y + q1.z*x1.z + q1.w*x1.w;
        float4 y0 = ((const float4*)sibK)[sub], y1 = ((const float4*)sibK)[sub + 8];
        pd[1] = q0.x*y0.x + q0.y*y0.y + q0.z*y0.z + q0.w*y0.w
              + q1.x*y1.x + q1.y*y1.y + q1.z*y1.z + q1.w*y1.w;
    }
#pragma unroll
    for (int i = 2; i < 13; i++) {
        const float4* kr = (const float4*)(sK + rows[i - 2] * DD);
        float4 x0 = kr[sub], x1 = kr[sub + 8];
        pd[i] = q0.x*x0.x + q0.y*x0.y + q0.z*x0.z + q0.w*x0.w
              + q1.x*x1.x + q1.y*x1.y + q1.z*x1.z + q1.w*x1.w;
    }
#pragma unroll
    for (int o = 4; o; o >>= 1) {
#pragma unroll
        for (int i = 0; i < 13; i++)
            pd[i] += __shfl_xor_sync(0xffffffffu, pd[i], o);
    }
    float m = -1e30f;
#pragma unroll
    for (int i = 0; i < 13; i++) {
        pd[i] = val[i] ? pd[i] * SCALE : -1e30f;
        m = fmaxf(m, pd[i]);
    }
    float denom = 0.0f;
#pragma unroll
    for (int i = 0; i < 13; i++) {
        pd[i] = __expf(pd[i] - m);
        denom += pd[i];
    }
    float4 a0, a1;
    {
        float4 y0 = ((const float4*)selfV)[sub], y1 = ((const float4*)selfV)[sub + 8];
        float w = pd[0];
        a0.x = w * y0.x; a0.y = w * y0.y; a0.z = w * y0.z; a0.w = w * y0.w;
        a1.x = w * y1.x; a1.y = w * y1.y; a1.z = w * y1.z; a1.w = w * y1.w;
        float4 z0 = ((const float4*)sibV)[sub], z1 = ((const float4*)sibV)[sub + 8];
        w = pd[1];
        a0.x += w * z0.x; a0.y += w * z0.y; a0.z += w * z0.z; a0.w += w * z0.w;
        a1.x += w * z1.x; a1.y += w * z1.y; a1.z += w * z1.z; a1.w += w * z1.w;
    }
#pragma unroll
    for (int i = 2; i < 13; i++) {
        const float4* vr = (const float4*)(sV + rows[i - 2] * DD);
        float4 y0 = vr[sub], y1 = vr[sub + 8];
        float w = pd[i];
        a0.x += w * y0.x; a0.y += w * y0.y; a0.z += w * y0.z; a0.w += w * y0.w;
        a1.x += w * y1.x; a1.y += w * y1.y; a1.z += w * y1.z; a1.w += w * y1.w;
    }
    float inv = 1.0f / denom;
    a0.x *= inv; a0.y *= inv; a0.z *= inv; a0.w *= inv;
    a1.x *= inv; a1.y *= inv; a1.z *= inv; a1.w *= inv;
    ((float4*)(out + qoff))[sub]     = a0;
    ((float4*)(out + qoff))[sub + 8] = a1;
}

extern "C" void kernel_launch(void* const* d_in, const int* in_sizes, int n_in,
                              void* d_out, int out_size) {
    const float* q = (const float*)d_in[0];
    const float* k = (const float*)d_in[1];
    const float* v = (const float*)d_in[2];
    float* out = (float*)d_out;

    build5<<<NBH * CPB, 128>>>(k, v);
    build_high<<<NBH, 512>>>();
    attn<<<NBH * CPB, 256>>>(q, k, v, out);
}

// round 6
// speedup vs baseline: 1.6143x; 1.0615x over previous
#include <cuda_runtime.h>
#include <math.h>

#define BB 4
#define SS 4096
#define HH 8
#define DD 64
#define HD (HH*DD)
#define SCALE 0.125f
#define NBH (BB*HH)          // 32 (b,h) pairs
#define CH 32                // leaves per chunk
#define CPB (SS/CH)          // 128 chunks per bh
#define HI_NODES 254         // levels 5..11 per bh

// Global storage for tree levels 5..11 only (~2MB each, L2-resident).
__device__ float g_hiK[(size_t)NBH * HI_NODES * DD];
__device__ float g_hiV[(size_t)NBH * HI_NODES * DD];

__device__ __forceinline__ int hioff(int j) { return 256 - (256 >> j); }

// ---------- 8-lane-group softmax pool ----------
__device__ __forceinline__ void pool8(const float* __restrict__ kc0,
                                      const float* __restrict__ kc1,
                                      const float* __restrict__ vc0,
                                      const float* __restrict__ vc1,
                                      float* __restrict__ kout,
                                      float* __restrict__ vout,
                                      int sub, unsigned mask) {
    float4 a0 = ((const float4*)kc0)[sub], a1 = ((const float4*)kc0)[sub + 8];
    float4 b0 = ((const float4*)kc1)[sub], b1 = ((const float4*)kc1)[sub + 8];
    float4 p0, p1;
    p0.x = 0.5f * (a0.x + b0.x); p0.y = 0.5f * (a0.y + b0.y);
    p0.z = 0.5f * (a0.z + b0.z); p0.w = 0.5f * (a0.w + b0.w);
    p1.x = 0.5f * (a1.x + b1.x); p1.y = 0.5f * (a1.y + b1.y);
    p1.z = 0.5f * (a1.z + b1.z); p1.w = 0.5f * (a1.w + b1.w);
    float ds = p0.x*p0.x + p0.y*p0.y + p0.z*p0.z + p0.w*p0.w
             + p1.x*p1.x + p1.y*p1.y + p1.z*p1.z + p1.w*p1.w;
    float d0 = p0.x*a0.x + p0.y*a0.y + p0.z*a0.z + p0.w*a0.w
             + p1.x*a1.x + p1.y*a1.y + p1.z*a1.z + p1.w*a1.w;
    float d1 = p0.x*b0.x + p0.y*b0.y + p0.z*b0.z + p0.w*b0.w
             + p1.x*b1.x + p1.y*b1.y + p1.z*b1.z + p1.w*b1.w;
#pragma unroll
    for (int o = 4; o; o >>= 1) {
        ds += __shfl_xor_sync(mask, ds, o);
        d0 += __shfl_xor_sync(mask, d0, o);
        d1 += __shfl_xor_sync(mask, d1, o);
    }
    float ss = ds * SCALE, s0 = d0 * SCALE, s1 = d1 * SCALE;
    float m  = fmaxf(ss, fmaxf(s0, s1));
    float es = __expf(ss - m), e0 = __expf(s0 - m), e1 = __expf(s1 - m);
    float inv = 1.0f / (es + e0 + e1 + 1e-9f);
    float hes = 0.5f * es;
    float4 va0 = ((const float4*)vc0)[sub], va1 = ((const float4*)vc0)[sub + 8];
    float4 vb0 = ((const float4*)vc1)[sub], vb1 = ((const float4*)vc1)[sub + 8];
    float4 o0, o1;
    o0.x = (hes*(va0.x+vb0.x) + e0*va0.x + e1*vb0.x) * inv;
    o0.y = (hes*(va0.y+vb0.y) + e0*va0.y + e1*vb0.y) * inv;
    o0.z = (hes*(va0.z+vb0.z) + e0*va0.z + e1*vb0.z) * inv;
    o0.w = (hes*(va0.w+vb0.w) + e0*va0.w + e1*vb0.w) * inv;
    o1.x = (hes*(va1.x+vb1.x) + e0*va1.x + e1*vb1.x) * inv;
    o1.y = (hes*(va1.y+vb1.y) + e0*va1.y + e1*vb1.y) * inv;
    o1.z = (hes*(va1.z+vb1.z) + e0*va1.z + e1*vb1.z) * inv;
    o1.w = (hes*(va1.w+vb1.w) + e0*va1.w + e1*vb1.w) * inv;
    ((float4*)kout)[sub] = p0;  ((float4*)kout)[sub + 8] = p1;
    ((float4*)vout)[sub] = o0;  ((float4*)vout)[sub + 8] = o1;
}

// Warp-collective full-dim pool for build_high only.
__device__ __forceinline__ void poolp(const float* __restrict__ kc0,
                                      const float* __restrict__ kc1,
                                      const float* __restrict__ vc0,
                                      const float* __restrict__ vc1,
                                      float* __restrict__ kout,
                                      float* __restrict__ vout, int lane) {
    float2 a  = *(const float2*)(kc0 + 2 * lane);
    float2 b  = *(const float2*)(kc1 + 2 * lane);
    float2 va = *(const float2*)(vc0 + 2 * lane);
    float2 vb = *(const float2*)(vc1 + 2 * lane);
    float2 kp;
    kp.x = 0.5f * (a.x + b.x);
    kp.y = 0.5f * (a.y + b.y);
    float ds = kp.x * kp.x + kp.y * kp.y;
    float d0 = kp.x * a.x + kp.y * a.y;
    float d1 = kp.x * b.x + kp.y * b.y;
#pragma unroll
    for (int o = 16; o; o >>= 1) {
        ds += __shfl_xor_sync(0xffffffffu, ds, o);
        d0 += __shfl_xor_sync(0xffffffffu, d0, o);
        d1 += __shfl_xor_sync(0xffffffffu, d1, o);
    }
    float ss = ds * SCALE, s0 = d0 * SCALE, s1 = d1 * SCALE;
    float m  = fmaxf(ss, fmaxf(s0, s1));
    float es = __expf(ss - m), e0 = __expf(s0 - m), e1 = __expf(s1 - m);
    float inv = 1.0f / (es + e0 + e1 + 1e-9f);
    float hes = 0.5f * es;
    float2 vp;
    vp.x = (hes * (va.x + vb.x) + e0 * va.x + e1 * vb.x) * inv;
    vp.y = (hes * (va.y + vb.y) + e0 * va.y + e1 * vb.y) * inv;
    *(float2*)(kout + 2 * lane) = kp;
    *(float2*)(vout + 2 * lane) = vp;
}

// ---------- Pass 1: per 32-leaf chunk, emit level-5 node ----------
__global__ __launch_bounds__(128) void build5(const float* __restrict__ k,
                                              const float* __restrict__ v) {
    __shared__ float sK[30 * DD], sV[30 * DD];
    int blk = blockIdx.x;
    int cc  = blk & (CPB - 1);
    int bh  = blk >> 7;
    int b = bh >> 3, h = bh & 7;
    int tid = threadIdx.x, warp = tid >> 5, lane = tid & 31;
    int g = lane >> 3, sub = lane & 7;
    unsigned gmask = 0xFFu << (g * 8);
    int slot = warp * 4 + g;

    const float* leafK = k + ((size_t)(b * SS + cc * CH) * HH + h) * DD;
    const float* leafV = v + ((size_t)(b * SS + cc * CH) * HH + h) * DD;

    pool8(leafK + (size_t)(2 * slot) * HD, leafK + (size_t)(2 * slot + 1) * HD,
          leafV + (size_t)(2 * slot) * HD, leafV + (size_t)(2 * slot + 1) * HD,
          sK + slot * DD, sV + slot * DD, sub, gmask);
    __syncthreads();
    if (slot < 8)
        pool8(sK + (2 * slot) * DD, sK + (2 * slot + 1) * DD,
              sV + (2 * slot) * DD, sV + (2 * slot + 1) * DD,
              sK + (16 + slot) * DD, sV + (16 + slot) * DD, sub, gmask);
    __syncthreads();
    if (warp == 0) {
        pool8(sK + (16 + 2 * g) * DD, sK + (16 + 2 * g + 1) * DD,
              sV + (16 + 2 * g) * DD, sV + (16 + 2 * g + 1) * DD,
              sK + (24 + g) * DD, sV + (24 + g) * DD, sub, gmask);
        __syncwarp();
        if (g < 2)
            pool8(sK + (24 + 2 * g) * DD, sK + (24 + 2 * g + 1) * DD,
                  sV + (24 + 2 * g) * DD, sV + (24 + 2 * g + 1) * DD,
                  sK + (28 + g) * DD, sV + (28 + g) * DD, sub, gmask);
        __syncwarp();
        if (g == 0) {
            size_t o = ((size_t)bh * HI_NODES + cc) * DD;
            pool8(sK + 28 * DD, sK + 29 * DD, sV + 28 * DD, sV + 29 * DD,
                  g_hiK + o, g_hiV + o, sub, 0xFFu);
        }
    }
}

// ---------- Pass 2: per bh, levels 6..11 ----------
__global__ __launch_bounds__(512) void build_high() {
    int bh = blockIdx.x;
    int warp = threadIdx.x >> 5, lane = threadIdx.x & 31;
    size_t base = (size_t)bh * HI_NODES * DD;

    int off_prev = 0, off = 128, cnt = 64;
#pragma unroll
    for (int l = 6; l <= 11; l++) {
        for (int j = warp; j < cnt; j += 16)
            poolp(g_hiK + base + (size_t)(off_prev + 2 * j) * DD,
                  g_hiK + base + (size_t)(off_prev + 2 * j + 1) * DD,
                  g_hiV + base + (size_t)(off_prev + 2 * j) * DD,
                  g_hiV + base + (size_t)(off_prev + 2 * j + 1) * DD,
                  g_hiK + base + (size_t)(off + j) * DD,
                  g_hiV + base + (size_t)(off + j) * DD, lane);
        __syncthreads();
        off_prev = off;
        off += cnt;
        cnt >>= 1;
    }
}

// ---------- Pass 3: fused attention, predicated per-slot work ----------
// Smem rows: L1 0..15, L2 16..23, L3 24..27, L4 28..29, HI 30..36 (37 rows).
#define R_L2 16
#define R_L3 24
#define R_L4 28
#define R_HI 30

__device__ __forceinline__ float4 lds4_pred(const float4* p, bool pr) {
    float4 r = {0.f, 0.f, 0.f, 0.f};
    if (pr) r = *p;
    return r;
}

__global__ __launch_bounds__(256) void attn(const float* __restrict__ q,
                                            const float* __restrict__ k,
                                            const float* __restrict__ v,
                                            float* __restrict__ out) {
    __shared__ float sK[37 * DD], sV[37 * DD];
    int blk = blockIdx.x;
    int cc  = blk & (CPB - 1);
    int bh  = blk >> 7;
    int b = bh >> 3, h = bh & 7;
    int tid = threadIdx.x, warp = tid >> 5, lane = tid & 31;
    int g = lane >> 3, sub = lane & 7;
    unsigned gmask = 0xFFu << (g * 8);
    int qid = tid >> 3;

    const float* leafK = k + ((size_t)(b * SS + cc * CH) * HH + h) * DD;
    const float* leafV = v + ((size_t)(b * SS + cc * CH) * HH + h) * DD;

    size_t qoff = ((size_t)(b * SS + cc * CH + qid) * HH + h) * DD;
    float4 q0 = ((const float4*)(q + qoff))[sub];
    float4 q1 = ((const float4*)(q + qoff))[sub + 8];

    if (warp < 4) {
        int slot = warp * 4 + g;
        pool8(leafK + (size_t)(2 * slot) * HD, leafK + (size_t)(2 * slot + 1) * HD,
              leafV + (size_t)(2 * slot) * HD, leafV + (size_t)(2 * slot + 1) * HD,
              sK + slot * DD, sV + slot * DD, sub, gmask);
    } else {
        int j = (warp - 4) * 4 + g;
        if (j < 7) {
            int n = cc >> j;
            int node = (n > 0) ? n - 1 : 0;
            const float* hk = g_hiK + ((size_t)bh * HI_NODES + hioff(j) + node) * DD;
            const float* hv = g_hiV + ((size_t)bh * HI_NODES + hioff(j) + node) * DD;
            ((float4*)(sK + (R_HI + j) * DD))[sub]     = ((const float4*)hk)[sub];
            ((float4*)(sK + (R_HI + j) * DD))[sub + 8] = ((const float4*)hk)[sub + 8];
            ((float4*)(sV + (R_HI + j) * DD))[sub]     = ((const float4*)hv)[sub];
            ((float4*)(sV + (R_HI + j) * DD))[sub + 8] = ((const float4*)hv)[sub + 8];
        }
    }
    __syncthreads();
    if (warp < 2) {
        int slot = warp * 4 + g;
        pool8(sK + (2 * slot) * DD, sK + (2 * slot + 1) * DD,
              sV + (2 * slot) * DD, sV + (2 * slot + 1) * DD,
              sK + (R_L2 + slot) * DD, sV + (R_L2 + slot) * DD, sub, gmask);
    }
    __syncthreads();
    if (warp == 0) {
        pool8(sK + (R_L2 + 2 * g) * DD, sK + (R_L2 + 2 * g + 1) * DD,
              sV + (R_L2 + 2 * g) * DD, sV + (R_L2 + 2 * g + 1) * DD,
              sK + (R_L3 + g) * DD, sV + (R_L3 + g) * DD, sub, gmask);
        __syncwarp();
        if (g < 2)
            pool8(sK + (R_L3 + 2 * g) * DD, sK + (R_L3 + 2 * g + 1) * DD,
                  sV + (R_L3 + 2 * g) * DD, sV + (R_L3 + 2 * g + 1) * DD,
                  sK + (R_L4 + g) * DD, sV + (R_L4 + g) * DD, sub, gmask);
    }
    __syncthreads();

    // ---- batched 13-key attention for query qid (predicated slots) ----
    const float* selfK = leafK + (size_t)qid * HD;
    const float* selfV = leafV + (size_t)qid * HD;
    int sib = (qid > 0) ? qid - 1 : 0;
    const float* sibK = leafK + (size_t)sib * HD;
    const float* sibV = leafV + (size_t)sib * HD;

    int rows[11];
    bool val[13];
    val[0] = true;
    val[1] = (qid & 1);
    const int tbase[4] = {0, R_L2, R_L3, R_L4};
#pragma unroll
    for (int l = 1; l <= 4; l++) {
        int n = qid >> l;
        rows[l - 1] = tbase[l - 1] + ((n > 0) ? n - 1 : 0);
        val[1 + l]  = (n & 1);
    }
#pragma unroll
    for (int j = 0; j < 7; j++) {
        rows[4 + j] = R_HI + j;
        val[6 + j]  = ((cc >> j) & 1);
    }

    // K pass: predicated loads — invalid slots move no bytes
    float pd[13];
    {
        float4 x0 = ((const float4*)selfK)[sub], x1 = ((const float4*)selfK)[sub + 8];
        pd[0] = q0.x*x0.x + q0.y*x0.y + q0.z*x0.z + q0.w*x0.w
              + q1.x*x1.x + q1.y*x1.y + q1.z*x1.z + q1.w*x1.w;
        float4 y0 = lds4_pred((const float4*)sibK + sub, val[1]);
        float4 y1 = lds4_pred((const float4*)sibK + sub + 8, val[1]);
        pd[1] = q0.x*y0.x + q0.y*y0.y + q0.z*y0.z + q0.w*y0.w
              + q1.x*y1.x + q1.y*y1.y + q1.z*y1.z + q1.w*y1.w;
    }
#pragma unroll
    for (int i = 2; i < 13; i++) {
        const float4* kr = (const float4*)(sK + rows[i - 2] * DD);
        float4 x0 = lds4_pred(kr + sub, val[i]);
        float4 x1 = lds4_pred(kr + sub + 8, val[i]);
        pd[i] = q0.x*x0.x + q0.y*x0.y + q0.z*x0.z + q0.w*x0.w
              + q1.x*x1.x + q1.y*x1.y + q1.z*x1.z + q1.w*x1.w;
    }
#pragma unroll
    for (int o = 4; o; o >>= 1) {
#pragma unroll
        for (int i = 0; i < 13; i++)
            pd[i] += __shfl_xor_sync(0xffffffffu, pd[i], o);
    }
    float m = -1e30f;
#pragma unroll
    for (int i = 0; i < 13; i++) {
        pd[i] = val[i] ? pd[i] * SCALE : -1e30f;
        m = fmaxf(m, pd[i]);
    }
    float denom = 0.0f;
#pragma unroll
    for (int i = 0; i < 13; i++) {
        pd[i] = val[i] ? __expf(pd[i] - m) : 0.0f;
        denom += pd[i];
    }
    // V pass: predicated loads
    float4 a0, a1;
    {
        float4 y0 = ((const float4*)selfV)[sub], y1 = ((const float4*)selfV)[sub + 8];
        float w = pd[0];
        a0.x = w * y0.x; a0.y = w * y0.y; a0.z = w * y0.z; a0.w = w * y0.w;
        a1.x = w * y1.x; a1.y = w * y1.y; a1.z = w * y1.z; a1.w = w * y1.w;
        float4 z0 = lds4_pred((const float4*)sibV + sub, val[1]);
        float4 z1 = lds4_pred((const float4*)sibV + sub + 8, val[1]);
        w = pd[1];
        a0.x += w * z0.x; a0.y += w * z0.y; a0.z += w * z0.z; a0.w += w * z0.w;
        a1.x += w * z1.x; a1.y += w * z1.y; a1.z += w * z1.z; a1.w += w * z1.w;
    }
#pragma unroll
    for (int i = 2; i < 13; i++) {
        const float4* vr = (const float4*)(sV + rows[i - 2] * DD);
        float4 y0 = lds4_pred(vr + sub, val[i]);
        float4 y1 = lds4_pred(vr + sub + 8, val[i]);
        float w = pd[i];
        a0.x += w * y0.x; a0.y += w * y0.y; a0.z += w * y0.z; a0.w += w * y0.w;
        a1.x += w * y1.x; a1.y += w * y1.y; a1.z += w * y1.z; a1.w += w * y1.w;
    }
    float inv = 1.0f / denom;
    a0.x *= inv; a0.y *= inv; a0.z *= inv; a0.w *= inv;
    a1.x *= inv; a1.y *= inv; a1.z *= inv; a1.w *= inv;
    ((float4*)(out + qoff))[sub]     = a0;
    ((float4*)(out + qoff))[sub + 8] = a1;
}

extern "C" void kernel_launch(void* const* d_in, const int* in_sizes, int n_in,
                              void* d_out, int out_size) {
    const float* q = (const float*)d_in[0];
    const float* k = (const float*)d_in[1];
    const float* v = (const float*)d_in[2];
    float* out = (float*)d_out;

    build5<<<NBH * CPB, 128>>>(k, v);
    build_high<<<NBH, 512>>>();
    attn<<<NBH * CPB, 256>>>(q, k, v, out);
}